// round 5
// baseline (speedup 1.0000x reference)
#include <cuda_runtime.h>

#define NN      25200
#define KSEL    2048
#define NCLS    80
#define CONF_T  0.4f
#define IOU_T   0.45f
#define MAXDET  1000
#define MAXWH   7680.0f
#define ROWW    32          /* 2048/64 uint64 words per mask row */
#define IMG_PIX (640*640)

/* ---------------- scratch (device globals; no allocation) ---------------- */
__device__ float              g_scores[NN];
__device__ float              g_cls[NN];
__device__ unsigned           g_key32[NN];
__device__ int                g_sortedIdx[KSEL];
__device__ float              g_topS[KSEL];
__device__ float4             g_b[KSEL];      /* unshifted xyxy of sorted cands */
__device__ float              g_c[KSEL];      /* class as float */
__device__ float4             g_boff[KSEL];   /* class-offset boxes for IoU */
__device__ unsigned long long g_maskM[KSEL * ROWW]; /* suppression bitmatrix */
__device__ unsigned long long g_keep[ROWW];

/* ---------------- stage 1: per-anchor conf / cls / sortable key ---------- */
__global__ void prep_kernel(const float* __restrict__ pred) {
    int anchor = (blockIdx.x * blockDim.x + threadIdx.x) >> 5;
    int lane   = threadIdx.x & 31;
    if (anchor >= NN) return;
    const float* row = pred + (long long)anchor * 85;
    float obj = row[4];
    float best = -1.0f;
    int   bc   = 0;
    for (int j = lane; j < NCLS; j += 32) {
        float v = __fmul_rn(row[5 + j], obj);
        if (v > best) { best = v; bc = j; }       /* strict > -> first max */
    }
    /* warp argmax, ties -> lowest class index (jnp.argmax semantics) */
    for (int off = 16; off; off >>= 1) {
        float ov = __shfl_down_sync(0xffffffffu, best, off);
        int   oc = __shfl_down_sync(0xffffffffu, bc, off);
        if (ov > best || (ov == best && oc < bc)) { best = ov; bc = oc; }
    }
    if (lane == 0) {
        float s = (best > CONF_T) ? best : -1.0f;
        g_scores[anchor] = s;
        g_cls[anchor]    = (float)bc;
        unsigned u = __float_as_uint(s);
        g_key32[anchor] = (u >> 31) ? ~u : (u | 0x80000000u);  /* order-preserving */
    }
}

/* ---------------- stage 2: radix-select threshold + bitonic top-2048 ----- */
__global__ void topk_kernel() {
    __shared__ int bins[256];
    __shared__ int s_sel, s_acc, s_cnt;
    __shared__ unsigned long long key64[KSEL];
    int tid = threadIdx.x;

    /* 4x8-bit radix select: find T = 2048th-largest key */
    unsigned prefixv = 0;
    int need = KSEL;
    for (int shift = 24; shift >= 0; shift -= 8) {
        for (int b = tid; b < 256; b += blockDim.x) bins[b] = 0;
        __syncthreads();
        unsigned hmask = (shift == 24) ? 0u : (0xFFFFFFFFu << (shift + 8));
        for (int i = tid; i < NN; i += blockDim.x) {
            unsigned k = g_key32[i];
            if ((k & hmask) == prefixv) atomicAdd(&bins[(k >> shift) & 255], 1);
        }
        __syncthreads();
        if (tid == 0) {
            int acc = 0, v = 0;
            for (int b = 255; b >= 0; b--) {
                if (acc + bins[b] >= need) { v = b; break; }
                acc += bins[b];
            }
            s_sel = v; s_acc = acc;
        }
        __syncthreads();
        prefixv |= ((unsigned)s_sel) << shift;
        need -= s_acc;
        __syncthreads();
    }

    /* gather all keys >= T (guaranteed >= 2048 exist), cap at 2048 */
    if (tid == 0) s_cnt = 0;
    __syncthreads();
    for (int i = tid; i < NN; i += blockDim.x) {
        unsigned k = g_key32[i];
        if (k >= prefixv) {
            int p = atomicAdd(&s_cnt, 1);
            if (p < KSEL)
                key64[p] = (((unsigned long long)k) << 32) | (unsigned)(~(unsigned)i);
        }
    }
    __syncthreads();

    /* bitonic sort 2048 keys, descending; ~index in low bits => lowest index
       wins ties, and gather order becomes irrelevant (deterministic output) */
    for (unsigned k = 2; k <= KSEL; k <<= 1) {
        for (unsigned j = k >> 1; j; j >>= 1) {
            for (unsigned t = tid; t < KSEL; t += blockDim.x) {
                unsigned l = t ^ j;
                if (l > t) {
                    unsigned long long a = key64[t], b = key64[l];
                    bool descBlk = ((t & k) == 0);
                    bool sw = descBlk ? (a < b) : (a > b);
                    if (sw) { key64[t] = b; key64[l] = a; }
                }
            }
            __syncthreads();
        }
    }
    for (int t = tid; t < KSEL; t += blockDim.x) {
        unsigned long long kk = key64[t];
        int idx = (int)(~(unsigned)(kk & 0xFFFFFFFFull));
        g_sortedIdx[t] = idx;
        g_topS[t]      = g_scores[idx];
    }
}

/* ---------------- stage 3: gather boxes + class offsets ------------------ */
__global__ void gather_kernel(const float* __restrict__ pred) {
    int i = blockIdx.x * blockDim.x + threadIdx.x;
    if (i >= KSEL) return;
    int idx = g_sortedIdx[i];
    const float* row = pred + (long long)idx * 85;
    float x = row[0], y = row[1], w = row[2], h = row[3];
    float hw = __fmul_rn(w, 0.5f), hh = __fmul_rn(h, 0.5f);
    float4 b;
    b.x = __fsub_rn(x, hw); b.y = __fsub_rn(y, hh);
    b.z = __fadd_rn(x, hw); b.w = __fadd_rn(y, hh);
    float c   = g_cls[idx];
    float off = __fmul_rn(c, MAXWH);
    float4 bo;
    bo.x = __fadd_rn(b.x, off); bo.y = __fadd_rn(b.y, off);
    bo.z = __fadd_rn(b.z, off); bo.w = __fadd_rn(b.w, off);
    g_b[i] = b; g_c[i] = c; g_boff[i] = bo;
}

/* ---------------- stage 4: parallel 2048x2048 suppression bitmask -------- */
__global__ void mask_kernel() {
    __shared__ float4 jb[64];
    int jblk = blockIdx.x, iblk = blockIdx.y;
    int tid = threadIdx.x;
    jb[tid] = g_boff[jblk * 64 + tid];
    __syncthreads();
    int i = iblk * 64 + tid;
    float4 a = g_boff[i];
    float areaA = __fmul_rn(__fsub_rn(a.z, a.x), __fsub_rn(a.w, a.y));
    unsigned long long bits = 0;
    int jbase = jblk * 64;
    #pragma unroll 8
    for (int jj = 0; jj < 64; jj++) {
        int j = jbase + jj;
        if (j <= i) continue;                  /* ar > i */
        float4 bb = jb[jj];
        float lx = fmaxf(a.x, bb.x), ly = fmaxf(a.y, bb.y);
        float rx = fminf(a.z, bb.z), ry = fminf(a.w, bb.w);
        float w = fmaxf(__fsub_rn(rx, lx), 0.0f);
        float h = fmaxf(__fsub_rn(ry, ly), 0.0f);
        float inter = __fmul_rn(w, h);
        float areaB = __fmul_rn(__fsub_rn(bb.z, bb.x), __fsub_rn(bb.w, bb.y));
        float denom = __fadd_rn(__fsub_rn(__fadd_rn(areaA, areaB), inter), 1e-7f);
        float iou = __fdiv_rn(inter, denom);
        if (iou > IOU_T) bits |= (1ull << jj);
    }
    g_maskM[(long long)i * ROWW + jblk] = bits;
}

/* ---------------- stage 5: serial greedy suppression (1 warp) ------------ */
__global__ void nms_kernel() {
    int lane = threadIdx.x;                    /* lane owns bits [64l, 64l+64) */
    unsigned long long alive = 0;
    for (int b = 0; b < 64; b++)
        if (g_topS[lane * 64 + b] > CONF_T) alive |= (1ull << b);
    unsigned long long row = g_maskM[lane];    /* row for i=0 */
    for (int i = 0; i < KSEL; i++) {
        unsigned long long nrow =
            (i + 1 < KSEL) ? g_maskM[(long long)(i + 1) * ROWW + lane] : 0ull;
        unsigned long long aw = __shfl_sync(0xffffffffu, alive, i >> 6);
        if ((aw >> (i & 63)) & 1ull) alive &= ~row;
        row = nrow;
    }
    g_keep[lane] = alive;
}

/* ---------------- stage 6: compact survivors -> det[1000][6] ------------- */
__global__ void finalize_kernel(float* __restrict__ out) {
    __shared__ unsigned long long kw[ROWW];
    __shared__ int wpre[ROWW + 1];
    int tid = threadIdx.x;
    for (int e = tid; e < MAXDET * 6; e += blockDim.x) out[e] = 0.0f;
    if (tid < ROWW) kw[tid] = g_keep[tid];
    __syncthreads();
    if (tid == 0) {
        int acc = 0;
        for (int w = 0; w < ROWW; w++) { wpre[w] = acc; acc += __popcll(kw[w]); }
        wpre[ROWW] = acc;
    }
    __syncthreads();
    for (int i = tid; i < KSEL; i += blockDim.x) {
        int w = i >> 6, b = i & 63;
        unsigned long long word = kw[w];
        if ((word >> b) & 1ull) {
            int rank = wpre[w] + __popcll(word & ((1ull << b) - 1ull));
            if (rank < MAXDET) {
                float4 bb = g_b[i];
                float* o = out + rank * 6;
                o[0] = bb.x; o[1] = bb.y; o[2] = bb.z; o[3] = bb.w;
                o[4] = g_topS[i]; o[5] = g_c[i];
            }
        }
    }
}

/* ---------------- stage 7: image BGR/CHW/255 normalize ------------------- */
__global__ void img_kernel(const int* __restrict__ img, float* __restrict__ out) {
    int idx = blockIdx.x * blockDim.x + threadIdx.x;
    if (idx >= 3 * IMG_PIX) return;
    int c = idx / IMG_PIX;
    int r = idx - c * IMG_PIX;
    int v = img[r * 3 + (2 - c)];              /* [::-1] channel flip */
    out[idx] = __fdiv_rn((float)v, 255.0f);
}

/* ---------------- launch --------------------------------------------------- */
extern "C" void kernel_launch(void* const* d_in, const int* in_sizes, int n_in,
                              void* d_out, int out_size) {
    (void)in_sizes; (void)n_in; (void)out_size;
    const int*   img  = (const int*)d_in[0];
    const float* pred = (const float*)d_in[1];   /* batch 0 only is needed */
    float* out = (float*)d_out;                  /* [det(1000*6) | x(3*640*640)] */

    prep_kernel    <<<(NN + 7) / 8, 256>>>(pred);
    topk_kernel    <<<1, 1024>>>();
    gather_kernel  <<<(KSEL + 255) / 256, 256>>>(pred);
    mask_kernel    <<<dim3(32, 32), 64>>>();
    nms_kernel     <<<1, 32>>>();
    finalize_kernel<<<1, 1024>>>(out);
    img_kernel     <<<(3 * IMG_PIX + 255) / 256, 256>>>(img, out + MAXDET * 6);
}